// round 1
// baseline (speedup 1.0000x reference)
#include <cuda_runtime.h>
#include <cstdint>

#define BB   512
#define DD   128
#define SS   50
#define TT   32
#define LL   64
#define CLIPF 50
#define NF   10000

// ---- device scratch (no allocations allowed) ----
__device__ float g_mem[BB * DD];            // [B, D]
__device__ float g_sent[(size_t)BB * SS * DD]; // [B, S, D]
__device__ float g_sw[BB * SS];             // [B, S]

// ---------------------------------------------------------------
// mem = emb_item[item] @ W_mem + b_mem      grid=B, block=D
// ---------------------------------------------------------------
__global__ void k_init_mem(const int* __restrict__ item_idx,
                           const float* __restrict__ emb_item,
                           const float* __restrict__ W_mem,
                           const float* __restrict__ b_mem) {
    int b = blockIdx.x, d = threadIdx.x;
    __shared__ float it_s[LL];
    if (d < LL) it_s[d] = emb_item[(size_t)item_idx[b] * LL + d];
    __syncthreads();
    float acc = b_mem[d];
#pragma unroll
    for (int l = 0; l < LL; l++) acc += it_s[l] * W_mem[l * DD + d];
    g_mem[b * DD + d] = acc;
}

// ---------------------------------------------------------------
// Word-level attention for one (b, s):
//   tile = emb_word[uti[u, s, :]]               [T, D]
//   ww   = softmax_t(tile @ mem[b])
//   sentence[b,s] = ww @ tile
//   sw[b,s] = sentence . w_word + b_word
// grid = (B, S), block = 128
// ---------------------------------------------------------------
__global__ void k_word_attn(const int* __restrict__ user_idx,
                            const int* __restrict__ uti,
                            const float* __restrict__ emb_word,
                            const float* __restrict__ w_word,
                            const float* __restrict__ b_word) {
    int b = blockIdx.x, s = blockIdx.y;
    int tid = threadIdx.x, lane = tid & 31, warp = tid >> 5;

    __shared__ float tile[TT][DD];   // 16 KB
    __shared__ float mem_s[DD];
    __shared__ float sc[TT];
    __shared__ float wred[4];

    mem_s[tid] = g_mem[b * DD + tid];

    int u = user_idx[b];
    const int* idxp = uti + ((size_t)u * SS + s) * TT;

    // each warp gathers 8 rows; 32 lanes x float4 = 512B per row
    for (int t = warp; t < TT; t += 4) {
        int w = idxp[t];
        float4 v = reinterpret_cast<const float4*>(emb_word + (size_t)w * DD)[lane];
        reinterpret_cast<float4*>(&tile[t][0])[lane] = v;
    }
    __syncthreads();

    // scores: warp w handles t in [8w, 8w+8)
#pragma unroll
    for (int k = 0; k < 8; k++) {
        int t = warp * 8 + k;
        float p = tile[t][lane]      * mem_s[lane]
                + tile[t][lane + 32] * mem_s[lane + 32]
                + tile[t][lane + 64] * mem_s[lane + 64]
                + tile[t][lane + 96] * mem_s[lane + 96];
#pragma unroll
        for (int o = 16; o; o >>= 1) p += __shfl_xor_sync(0xffffffffu, p, o);
        if (lane == 0) sc[t] = p;
    }
    __syncthreads();

    // softmax over T (warp 0)
    if (warp == 0) {
        float v = sc[lane];
        float m = v;
#pragma unroll
        for (int o = 16; o; o >>= 1) m = fmaxf(m, __shfl_xor_sync(0xffffffffu, m, o));
        float e = expf(v - m);
        float sum = e;
#pragma unroll
        for (int o = 16; o; o >>= 1) sum += __shfl_xor_sync(0xffffffffu, sum, o);
        sc[lane] = e / sum;
    }
    __syncthreads();

    // sentence[d] = sum_t ww[t] * tile[t][d]
    float acc = 0.f;
#pragma unroll
    for (int t = 0; t < TT; t++) acc += sc[t] * tile[t][tid];
    g_sent[((size_t)b * SS + s) * DD + tid] = acc;

    // sw = sentence . w_word + b_word
    float p = acc * w_word[tid];
#pragma unroll
    for (int o = 16; o; o >>= 1) p += __shfl_xor_sync(0xffffffffu, p, o);
    if (lane == 0) wred[warp] = p;
    __syncthreads();
    if (tid == 0) g_sw[b * SS + s] = wred[0] + wred[1] + wred[2] + wred[3] + b_word[0];
}

// ---------------------------------------------------------------
// Sentence-level attention + mem update.  grid=B, block=128
// ---------------------------------------------------------------
__global__ void k_sent_attn(const float* __restrict__ w_sent,
                            const float* __restrict__ b_sent) {
    int b = blockIdx.x, tid = threadIdx.x, lane = tid & 31, warp = tid >> 5;
    __shared__ float wred[4];
    __shared__ float swf[SS];
    __shared__ float iw_s;

    float m = g_mem[b * DD + tid];

    // iw = mem . w_sent + b_sent
    float p = m * w_sent[tid];
#pragma unroll
    for (int o = 16; o; o >>= 1) p += __shfl_xor_sync(0xffffffffu, p, o);
    if (lane == 0) wred[warp] = p;
    __syncthreads();
    if (tid == 0) iw_s = wred[0] + wred[1] + wred[2] + wred[3] + b_sent[0];
    __syncthreads();

    // softmax over S of tanh(sw + iw)  (warp 0)
    if (warp == 0) {
        float iw = iw_s;
        float v0 = (lane < SS)      ? tanhf(g_sw[b * SS + lane] + iw)        : -1e30f;
        float v1 = (lane + 32 < SS) ? tanhf(g_sw[b * SS + lane + 32] + iw)   : -1e30f;
        float mx = fmaxf(v0, v1);
#pragma unroll
        for (int o = 16; o; o >>= 1) mx = fmaxf(mx, __shfl_xor_sync(0xffffffffu, mx, o));
        float e0 = (lane < SS)      ? expf(v0 - mx) : 0.f;
        float e1 = (lane + 32 < SS) ? expf(v1 - mx) : 0.f;
        float sum = e0 + e1;
#pragma unroll
        for (int o = 16; o; o >>= 1) sum += __shfl_xor_sync(0xffffffffu, sum, o);
        if (lane < SS)      swf[lane]      = e0 / sum;
        if (lane + 32 < SS) swf[lane + 32] = e1 / sum;
    }
    __syncthreads();

    // mem += sum_s swf[s] * sentence[b,s,:]
    float acc = m;
    const float* sp = g_sent + (size_t)b * SS * DD + tid;
#pragma unroll 5
    for (int s = 0; s < SS; s++) acc += swf[s] * sp[s * DD];
    g_mem[b * DD + tid] = acc;
}

// ---------------------------------------------------------------
// Final stage: ept, friend aggregation + group_idx, alpha MLP, rating.
// grid=B, block=64 (=L)
// ---------------------------------------------------------------
__global__ void k_final(const int* __restrict__ user_idx,
                        const int* __restrict__ item_idx,
                        const float* __restrict__ emb_item,
                        const float* __restrict__ emb_user,
                        const float* __restrict__ W_tr, const float* __restrict__ b_tr,
                        const float* __restrict__ W1,  const float* __restrict__ b1,
                        const float* __restrict__ W2,  const float* __restrict__ b2,
                        const float* __restrict__ W3,  const float* __restrict__ b3,
                        const float* __restrict__ w_aff, const float* __restrict__ b_aff,
                        const int* __restrict__ ufi,
                        float* __restrict__ out) {
    int b = blockIdx.x, l = threadIdx.x, lane = l & 31, warp = l >> 5;
    __shared__ float item_s[LL], a1[32], a2[16], alpha[2];
    __shared__ float upart[2][LL];
    __shared__ float red2[2];
    __shared__ int padc[2];

    float it = emb_item[(size_t)item_idx[b] * LL + l];
    item_s[l] = it;
    float waff_l = w_aff[l];
    float ba = b_aff[0];

    // ept[l] = mem[b] @ W_tr[:, l] + b_tr[l]
    float ept = b_tr[l];
    const float* memp = g_mem + b * DD;
#pragma unroll 8
    for (int d = 0; d < DD; d++) ept += memp[d] * W_tr[d * LL + l];
    __syncthreads();

    // alpha MLP
    if (l < 32) {
        float a = b1[l];
#pragma unroll
        for (int k = 0; k < LL; k++) a += item_s[k] * W1[k * 32 + l];
        a1[l] = 1.f / (1.f + expf(-a));
    }
    __syncthreads();
    if (l < 16) {
        float a = b2[l];
#pragma unroll
        for (int k = 0; k < 32; k++) a += a1[k] * W2[k * 16 + l];
        a2[l] = 1.f / (1.f + expf(-a));
    }
    __syncthreads();
    if (l < 2) {
        float a = b3[l];
#pragma unroll
        for (int k = 0; k < 16; k++) a += a2[k] * W3[k * 2 + l];
        alpha[l] = 1.f / (1.f + expf(-a));
    }

    // friend aggregation: warp w handles friends c = w, w+2, ...
    int u = user_idx[b];
    const int* fp = ufi + (size_t)u * CLIPF;
    float i0 = item_s[lane],       i1 = item_s[lane + 32];
    float w0 = w_aff[lane],        w1 = w_aff[lane + 32];
    float ua0 = 0.f, ua1 = 0.f;
    int pcount = 0;
    for (int c = warp; c < CLIPF; c += 2) {
        int f = fp[c];
        if (f == NF && lane == 0) pcount++;
        const float* fr = emb_user + (size_t)f * LL;
        float f0 = fr[lane], f1 = fr[lane + 32];
        float p = i0 * f0 * w0 + i1 * f1 * w1;
#pragma unroll
        for (int o = 16; o; o >>= 1) p += __shfl_xor_sync(0xffffffffu, p, o);
        float g = 1.f / (1.f + expf(-(p + ba)));
        if (lane == 0) out[BB + (size_t)b * CLIPF + c] = g;
        ua0 += f0 * g;
        ua1 += f1 * g;
    }
    upart[warp][lane] = ua0;
    upart[warp][lane + 32] = ua1;
    if (lane == 0) padc[warp] = pcount;
    __syncthreads();

    float fn = (float)CLIPF - (float)(padc[0] + padc[1]);
    float ue = (upart[0][l] + upart[1][l]) / fn;

    float vec = alpha[0] * ept + alpha[1] * ue;
    float p = vec * it * waff_l;
#pragma unroll
    for (int o = 16; o; o >>= 1) p += __shfl_xor_sync(0xffffffffu, p, o);
    if (lane == 0) red2[warp] = p;
    __syncthreads();
    if (l == 0) out[b] = 1.f / (1.f + expf(-(red2[0] + red2[1] + ba)));
}

// ---------------------------------------------------------------
extern "C" void kernel_launch(void* const* d_in, const int* in_sizes, int n_in,
                              void* d_out, int out_size) {
    const int*   user_idx = (const int*)d_in[0];
    const int*   item_idx = (const int*)d_in[1];
    const float* emb_word = (const float*)d_in[2];
    const float* emb_item = (const float*)d_in[3];
    const float* emb_user = (const float*)d_in[4];
    const float* W_mem    = (const float*)d_in[5];
    const float* b_mem    = (const float*)d_in[6];
    const float* w_word   = (const float*)d_in[7];
    const float* b_word   = (const float*)d_in[8];
    const float* w_sent   = (const float*)d_in[9];
    const float* b_sent   = (const float*)d_in[10];
    const float* W_tr     = (const float*)d_in[11];
    const float* b_tr     = (const float*)d_in[12];
    const float* W1       = (const float*)d_in[13];
    const float* b1       = (const float*)d_in[14];
    const float* W2       = (const float*)d_in[15];
    const float* b2       = (const float*)d_in[16];
    const float* W3       = (const float*)d_in[17];
    const float* b3       = (const float*)d_in[18];
    const float* w_aff    = (const float*)d_in[19];
    const float* b_aff    = (const float*)d_in[20];
    const int*   uti      = (const int*)d_in[21];
    const int*   ufi      = (const int*)d_in[22];
    float* out = (float*)d_out;

    k_init_mem<<<BB, DD>>>(item_idx, emb_item, W_mem, b_mem);
    dim3 gA(BB, SS);
    for (int h = 0; h < 2; h++) {
        k_word_attn<<<gA, 128>>>(user_idx, uti, emb_word, w_word, b_word);
        k_sent_attn<<<BB, 128>>>(w_sent, b_sent);
    }
    k_final<<<BB, LL>>>(user_idx, item_idx, emb_item, emb_user,
                        W_tr, b_tr, W1, b1, W2, b2, W3, b3,
                        w_aff, b_aff, ufi, out);
}

// round 2
// speedup vs baseline: 1.5551x; 1.5551x over previous
#include <cuda_runtime.h>
#include <cstdint>

#define BB   512
#define DD   128
#define SS   50
#define TT   32
#define LL   64
#define CLIPF 50
#define NF   10000

// ---- device scratch (no allocations allowed) ----
__device__ __align__(16) float g_mem[BB * DD];                // [B, D]
__device__ __align__(16) float g_sent[(size_t)BB * SS * DD];  // [B, S, D]
__device__ float g_sw[BB * SS];                               // [B, S]

// ---------------------------------------------------------------
// mem = emb_item[item] @ W_mem + b_mem      grid=B, block=D
// ---------------------------------------------------------------
__global__ void k_init_mem(const int* __restrict__ item_idx,
                           const float* __restrict__ emb_item,
                           const float* __restrict__ W_mem,
                           const float* __restrict__ b_mem) {
    int b = blockIdx.x, d = threadIdx.x;
    __shared__ float it_s[LL];
    if (d < LL) it_s[d] = emb_item[(size_t)item_idx[b] * LL + d];
    __syncthreads();
    float acc = b_mem[d];
#pragma unroll
    for (int l = 0; l < LL; l++) acc += it_s[l] * W_mem[l * DD + d];
    g_mem[b * DD + d] = acc;
}

// ---------------------------------------------------------------
// Word-level attention for one (b, s), register-resident tile.
// Warp w owns rows t in [8w, 8w+8); lane holds d = 4*lane..4*lane+3
// as float4. Scores + weighted sum fully in registers; only a
// 32-float score scratch + 4x128 partial buffer hit shared memory.
// grid = (B, S), block = 128
// ---------------------------------------------------------------
__global__ void __launch_bounds__(128)
k_word_attn(const int* __restrict__ user_idx,
            const int* __restrict__ uti,
            const float* __restrict__ emb_word,
            const float* __restrict__ w_word,
            const float* __restrict__ b_word) {
    int b = blockIdx.x, s = blockIdx.y;
    int tid = threadIdx.x, lane = tid & 31, warp = tid >> 5;

    __shared__ float sc[TT];          // scores / softmax weights
    __shared__ float part[4][DD];     // per-warp sentence partials (2KB)
    __shared__ float wred[4];

    // this lane's slice of mem (d = 4*lane .. 4*lane+3)
    float4 m4 = reinterpret_cast<const float4*>(g_mem + b * DD)[lane];

    int u = user_idx[b];
    const int* idxp = uti + ((size_t)u * SS + s) * TT + warp * 8;

    int widx[8];
#pragma unroll
    for (int k = 0; k < 8; k++) widx[k] = idxp[k];

    float4 r[8];
#pragma unroll
    for (int k = 0; k < 8; k++)
        r[k] = reinterpret_cast<const float4*>(emb_word + (size_t)widx[k] * DD)[lane];

    // scores for this warp's 8 rows: in-register dot + shuffle reduce
#pragma unroll
    for (int k = 0; k < 8; k++) {
        float p = r[k].x * m4.x + r[k].y * m4.y + r[k].z * m4.z + r[k].w * m4.w;
#pragma unroll
        for (int o = 16; o; o >>= 1) p += __shfl_xor_sync(0xffffffffu, p, o);
        if (lane == 0) sc[warp * 8 + k] = p;
    }
    __syncthreads();

    // softmax over T=32 (warp 0)
    if (warp == 0) {
        float v = sc[lane];
        float m = v;
#pragma unroll
        for (int o = 16; o; o >>= 1) m = fmaxf(m, __shfl_xor_sync(0xffffffffu, m, o));
        float e = expf(v - m);
        float sum = e;
#pragma unroll
        for (int o = 16; o; o >>= 1) sum += __shfl_xor_sync(0xffffffffu, sum, o);
        sc[lane] = e / sum;
    }
    __syncthreads();

    // weighted sum, in registers per warp
    float ww[8];
#pragma unroll
    for (int k = 0; k < 8; k++) ww[k] = sc[warp * 8 + k];

    float4 acc = make_float4(0.f, 0.f, 0.f, 0.f);
#pragma unroll
    for (int k = 0; k < 8; k++) {
        acc.x += ww[k] * r[k].x;
        acc.y += ww[k] * r[k].y;
        acc.z += ww[k] * r[k].z;
        acc.w += ww[k] * r[k].w;
    }
    reinterpret_cast<float4*>(&part[warp][0])[lane] = acc;
    __syncthreads();

    // final sentence[d], d = tid: sum the 4 warp partials
    float sd = part[0][tid] + part[1][tid] + part[2][tid] + part[3][tid];
    g_sent[((size_t)b * SS + s) * DD + tid] = sd;

    // sw = sentence . w_word + b_word
    float p = sd * w_word[tid];
#pragma unroll
    for (int o = 16; o; o >>= 1) p += __shfl_xor_sync(0xffffffffu, p, o);
    if (lane == 0) wred[warp] = p;
    __syncthreads();
    if (tid == 0) g_sw[b * SS + s] = wred[0] + wred[1] + wred[2] + wred[3] + b_word[0];
}

// ---------------------------------------------------------------
// Sentence-level attention + mem update.  grid=B, block=128
// ---------------------------------------------------------------
__global__ void k_sent_attn(const float* __restrict__ w_sent,
                            const float* __restrict__ b_sent) {
    int b = blockIdx.x, tid = threadIdx.x, lane = tid & 31, warp = tid >> 5;
    __shared__ float wred[4];
    __shared__ float swf[SS];
    __shared__ float iw_s;

    float m = g_mem[b * DD + tid];

    // iw = mem . w_sent + b_sent
    float p = m * w_sent[tid];
#pragma unroll
    for (int o = 16; o; o >>= 1) p += __shfl_xor_sync(0xffffffffu, p, o);
    if (lane == 0) wred[warp] = p;
    __syncthreads();
    if (tid == 0) iw_s = wred[0] + wred[1] + wred[2] + wred[3] + b_sent[0];
    __syncthreads();

    // softmax over S of tanh(sw + iw)  (warp 0)
    if (warp == 0) {
        float iw = iw_s;
        float v0 = (lane < SS)      ? tanhf(g_sw[b * SS + lane] + iw)        : -1e30f;
        float v1 = (lane + 32 < SS) ? tanhf(g_sw[b * SS + lane + 32] + iw)   : -1e30f;
        float mx = fmaxf(v0, v1);
#pragma unroll
        for (int o = 16; o; o >>= 1) mx = fmaxf(mx, __shfl_xor_sync(0xffffffffu, mx, o));
        float e0 = (lane < SS)      ? expf(v0 - mx) : 0.f;
        float e1 = (lane + 32 < SS) ? expf(v1 - mx) : 0.f;
        float sum = e0 + e1;
#pragma unroll
        for (int o = 16; o; o >>= 1) sum += __shfl_xor_sync(0xffffffffu, sum, o);
        if (lane < SS)      swf[lane]      = e0 / sum;
        if (lane + 32 < SS) swf[lane + 32] = e1 / sum;
    }
    __syncthreads();

    // mem += sum_s swf[s] * sentence[b,s,:]
    float acc = m;
    const float* sp = g_sent + (size_t)b * SS * DD + tid;
#pragma unroll 5
    for (int s = 0; s < SS; s++) acc += swf[s] * sp[s * DD];
    g_mem[b * DD + tid] = acc;
}

// ---------------------------------------------------------------
// Final stage: ept, friend aggregation + group_idx, alpha MLP, rating.
// grid=B, block=64 (=L)
// ---------------------------------------------------------------
__global__ void k_final(const int* __restrict__ user_idx,
                        const int* __restrict__ item_idx,
                        const float* __restrict__ emb_item,
                        const float* __restrict__ emb_user,
                        const float* __restrict__ W_tr, const float* __restrict__ b_tr,
                        const float* __restrict__ W1,  const float* __restrict__ b1,
                        const float* __restrict__ W2,  const float* __restrict__ b2,
                        const float* __restrict__ W3,  const float* __restrict__ b3,
                        const float* __restrict__ w_aff, const float* __restrict__ b_aff,
                        const int* __restrict__ ufi,
                        float* __restrict__ out) {
    int b = blockIdx.x, l = threadIdx.x, lane = l & 31, warp = l >> 5;
    __shared__ float item_s[LL], a1[32], a2[16], alpha[2];
    __shared__ float upart[2][LL];
    __shared__ float red2[2];
    __shared__ int padc[2];

    float it = emb_item[(size_t)item_idx[b] * LL + l];
    item_s[l] = it;
    float waff_l = w_aff[l];
    float ba = b_aff[0];

    // ept[l] = mem[b] @ W_tr[:, l] + b_tr[l]
    float ept = b_tr[l];
    const float* memp = g_mem + b * DD;
#pragma unroll 8
    for (int d = 0; d < DD; d++) ept += memp[d] * W_tr[d * LL + l];
    __syncthreads();

    // alpha MLP
    if (l < 32) {
        float a = b1[l];
#pragma unroll
        for (int k = 0; k < LL; k++) a += item_s[k] * W1[k * 32 + l];
        a1[l] = 1.f / (1.f + expf(-a));
    }
    __syncthreads();
    if (l < 16) {
        float a = b2[l];
#pragma unroll
        for (int k = 0; k < 32; k++) a += a1[k] * W2[k * 16 + l];
        a2[l] = 1.f / (1.f + expf(-a));
    }
    __syncthreads();
    if (l < 2) {
        float a = b3[l];
#pragma unroll
        for (int k = 0; k < 16; k++) a += a2[k] * W3[k * 2 + l];
        alpha[l] = 1.f / (1.f + expf(-a));
    }

    // friend aggregation: warp w handles friends c = w, w+2, ...
    int u = user_idx[b];
    const int* fp = ufi + (size_t)u * CLIPF;
    float i0 = item_s[lane],       i1 = item_s[lane + 32];
    float w0 = w_aff[lane],        w1 = w_aff[lane + 32];
    float ua0 = 0.f, ua1 = 0.f;
    int pcount = 0;
    for (int c = warp; c < CLIPF; c += 2) {
        int f = fp[c];
        if (f == NF && lane == 0) pcount++;
        const float* fr = emb_user + (size_t)f * LL;
        float f0 = fr[lane], f1 = fr[lane + 32];
        float p = i0 * f0 * w0 + i1 * f1 * w1;
#pragma unroll
        for (int o = 16; o; o >>= 1) p += __shfl_xor_sync(0xffffffffu, p, o);
        float g = 1.f / (1.f + expf(-(p + ba)));
        if (lane == 0) out[BB + (size_t)b * CLIPF + c] = g;
        ua0 += f0 * g;
        ua1 += f1 * g;
    }
    upart[warp][lane] = ua0;
    upart[warp][lane + 32] = ua1;
    if (lane == 0) padc[warp] = pcount;
    __syncthreads();

    float fn = (float)CLIPF - (float)(padc[0] + padc[1]);
    float ue = (upart[0][l] + upart[1][l]) / fn;

    float vec = alpha[0] * ept + alpha[1] * ue;
    float p = vec * it * waff_l;
#pragma unroll
    for (int o = 16; o; o >>= 1) p += __shfl_xor_sync(0xffffffffu, p, o);
    if (lane == 0) red2[warp] = p;
    __syncthreads();
    if (l == 0) out[b] = 1.f / (1.f + expf(-(red2[0] + red2[1] + ba)));
}

// ---------------------------------------------------------------
extern "C" void kernel_launch(void* const* d_in, const int* in_sizes, int n_in,
                              void* d_out, int out_size) {
    const int*   user_idx = (const int*)d_in[0];
    const int*   item_idx = (const int*)d_in[1];
    const float* emb_word = (const float*)d_in[2];
    const float* emb_item = (const float*)d_in[3];
    const float* emb_user = (const float*)d_in[4];
    const float* W_mem    = (const float*)d_in[5];
    const float* b_mem    = (const float*)d_in[6];
    const float* w_word   = (const float*)d_in[7];
    const float* b_word   = (const float*)d_in[8];
    const float* w_sent   = (const float*)d_in[9];
    const float* b_sent   = (const float*)d_in[10];
    const float* W_tr     = (const float*)d_in[11];
    const float* b_tr     = (const float*)d_in[12];
    const float* W1       = (const float*)d_in[13];
    const float* b1       = (const float*)d_in[14];
    const float* W2       = (const float*)d_in[15];
    const float* b2       = (const float*)d_in[16];
    const float* W3       = (const float*)d_in[17];
    const float* b3       = (const float*)d_in[18];
    const float* w_aff    = (const float*)d_in[19];
    const float* b_aff    = (const float*)d_in[20];
    const int*   uti      = (const int*)d_in[21];
    const int*   ufi      = (const int*)d_in[22];
    float* out = (float*)d_out;

    k_init_mem<<<BB, DD>>>(item_idx, emb_item, W_mem, b_mem);
    dim3 gA(BB, SS);
    for (int h = 0; h < 2; h++) {
        k_word_attn<<<gA, 128>>>(user_idx, uti, emb_word, w_word, b_word);
        k_sent_attn<<<BB, 128>>>(w_sent, b_sent);
    }
    k_final<<<BB, LL>>>(user_idx, item_idx, emb_item, emb_user,
                        W_tr, b_tr, W1, b1, W2, b2, W3, b3,
                        w_aff, b_aff, ufi, out);
}